// round 4
// baseline (speedup 1.0000x reference)
#include <cuda_runtime.h>
#include <math_constants.h>

#define BB 32
#define SS 4096
#define HH 1024
#define KSPLIT 16
#define KCH (HH / KSPLIT)   // 64
#define BG 8                 // batches per v_k block
#define NBG (BB / BG)        // 4 batch groups
#define HX (HH / 256)        // 4 h-tiles

// Scratch (allocation-free rule: __device__ globals; zero-initialized)
__device__ float g_vp[KSPLIT][BB * HH];    // split-K partials of v = hid @ W (2 MB)
__device__ float g_v[BB * HH];             // reduced v
__device__ unsigned int g_vcnt[NBG][HX];   // v_k segment completion counters
__device__ unsigned int g_cnt[BB];         // score_k per-batch completion counters

// ---------------------------------------------------------------------------
// v = hid @ W with split-K partials + fused last-block reduction.
// grid (HX, KSPLIT, NBG) = (4, 16, 4) = 256 blocks x 256 threads (~14 warps/SM).
// W loads pipelined 8-deep for MLP. bias term dropped (softmax shift-invariant).
// ---------------------------------------------------------------------------
__global__ void v_k(const float* __restrict__ hidden, const float* __restrict__ W) {
    __shared__ float sh[BG * KCH];  // 2 KB
    __shared__ unsigned int is_last;

    const int hx = blockIdx.x;
    const int ks = blockIdx.y;
    const int bg = blockIdx.z;
    const int k0 = ks * KCH;
    const int h  = hx * 256 + threadIdx.x;

    for (int i = threadIdx.x; i < BG * KCH; i += 256) {
        int j = i / KCH, k = i % KCH;
        sh[i] = hidden[(bg * BG + j) * HH + k0 + k];
    }
    __syncthreads();

    float acc[BG];
    #pragma unroll
    for (int j = 0; j < BG; j++) acc[j] = 0.f;

    for (int kk = 0; kk < KCH; kk += 8) {
        float wv[8];
        #pragma unroll
        for (int u = 0; u < 8; u++)
            wv[u] = W[(size_t)(k0 + kk + u) * HH + h];   // 8 independent LDGs
        #pragma unroll
        for (int u = 0; u < 8; u++)
            #pragma unroll
            for (int j = 0; j < BG; j++)
                acc[j] += sh[j * KCH + kk + u] * wv[u];
    }
    #pragma unroll
    for (int j = 0; j < BG; j++)
        g_vp[ks][(bg * BG + j) * HH + h] = acc[j];

    // ---- elect last KSPLIT-block for this (hx, bg) segment; reduce in place ----
    __threadfence();
    __syncthreads();
    if (threadIdx.x == 0)
        is_last = (atomicAdd(&g_vcnt[bg][hx], 1u) == KSPLIT - 1u) ? 1u : 0u;
    __syncthreads();
    if (!is_last) return;

    #pragma unroll
    for (int j = 0; j < BG; j++) {
        const int idx = (bg * BG + j) * HH + h;
        float s = 0.f;
        #pragma unroll
        for (int p = 0; p < KSPLIT; p++) s += __ldcg(&g_vp[p][idx]);  // L2-coherent
        g_v[idx] = s;
    }
    if (threadIdx.x == 0) g_vcnt[bg][hx] = 0u;  // reset for next graph replay
}

// ---------------------------------------------------------------------------
// Energies + fused softmax.
// grid (SS/32, BB) = (128, 32), block 256 = 8 warps x 4 rows/warp.
// Phase 1 (all blocks): out[b,s] = enc[b,s,:] . v[b,:]  (enc streamed __ldcs)
// Phase 2 (last block per batch row, elected via g_cnt): softmax in place.
// ---------------------------------------------------------------------------
__global__ void score_k(const float* __restrict__ enc, float* __restrict__ out) {
    __shared__ float4 sv[HH / 4];  // v[b] staged, 4 KB
    __shared__ float red[32];
    __shared__ float bcast;
    __shared__ unsigned int is_last;

    const int b = blockIdx.y;
    for (int i = threadIdx.x; i < HH / 4; i += 256)
        sv[i] = reinterpret_cast<const float4*>(g_v + b * HH)[i];
    __syncthreads();

    const int w = threadIdx.x >> 5, lane = threadIdx.x & 31;
    const int s0 = blockIdx.x * 32 + w * 4;

    #pragma unroll
    for (int r = 0; r < 4; r++) {
        const int s = s0 + r;
        const float4* row =
            reinterpret_cast<const float4*>(enc + (size_t)b * SS * HH + (size_t)s * HH);
        float acc = 0.f;
        #pragma unroll
        for (int i = 0; i < 8; i++) {
            float4 e = __ldcs(row + lane + i * 32);  // streaming: read-once data
            float4 v = sv[lane + i * 32];
            acc += e.x * v.x + e.y * v.y + e.z * v.z + e.w * v.w;
        }
        #pragma unroll
        for (int o = 16; o; o >>= 1) acc += __shfl_xor_sync(0xffffffffu, acc, o);
        if (lane == 0) out[b * SS + s] = acc;
    }

    // ---- release our writes, elect the last block for this batch row ----
    __threadfence();
    __syncthreads();
    if (threadIdx.x == 0) {
        unsigned int last = (atomicAdd(&g_cnt[b], 1u) == gridDim.x - 1u) ? 1u : 0u;
        is_last = last;
        if (last) g_cnt[b] = 0u;  // reset for next graph replay
    }
    __syncthreads();
    if (!is_last) return;
    __threadfence();  // acquire: all writers' stores now visible via L2

    // ---- softmax over out[b, 0:4096] with 256 threads, 16 elems/thread ----
    float* row = out + b * SS;
    float vals[16];
    float mx = -CUDART_INF_F;
    #pragma unroll
    for (int i = 0; i < 16; i++) {
        vals[i] = __ldcg(row + threadIdx.x + i * 256);  // L2-coherent read
        mx = fmaxf(mx, vals[i]);
    }
    #pragma unroll
    for (int o = 16; o; o >>= 1) mx = fmaxf(mx, __shfl_xor_sync(0xffffffffu, mx, o));
    if (lane == 0) red[w] = mx;
    __syncthreads();
    if (w == 0) {
        float m = (lane < 8) ? red[lane] : -CUDART_INF_F;
        #pragma unroll
        for (int o = 4; o; o >>= 1) m = fmaxf(m, __shfl_xor_sync(0xffffffffu, m, o));
        if (lane == 0) bcast = m;
    }
    __syncthreads();
    mx = bcast;

    float sum = 0.f;
    #pragma unroll
    for (int i = 0; i < 16; i++) {
        vals[i] = __expf(vals[i] - mx);
        sum += vals[i];
    }
    #pragma unroll
    for (int o = 16; o; o >>= 1) sum += __shfl_xor_sync(0xffffffffu, sum, o);
    if (lane == 0) red[w] = sum;
    __syncthreads();
    if (w == 0) {
        float s = (lane < 8) ? red[lane] : 0.f;
        #pragma unroll
        for (int o = 4; o; o >>= 1) s += __shfl_xor_sync(0xffffffffu, s, o);
        if (lane == 0) bcast = s;
    }
    __syncthreads();
    const float inv = 1.0f / bcast;

    #pragma unroll
    for (int i = 0; i < 16; i++)
        row[threadIdx.x + i * 256] = vals[i] * inv;
}

extern "C" void kernel_launch(void* const* d_in, const int* in_sizes, int n_in,
                              void* d_out, int out_size) {
    const float* hidden = (const float*)d_in[0];  // [B,1,H]
    const float* enc    = (const float*)d_in[1];  // [B,S,H]
    const float* W      = (const float*)d_in[2];  // [H,H]
    // d_in[3] = bias — unused: constant per row under softmax
    float* out = (float*)d_out;                   // [B,S]

    v_k<<<dim3(HX, KSPLIT, NBG), 256>>>(hidden, W);
    score_k<<<dim3(SS / 32, BB), 256>>>(enc, out);
}